// round 16
// baseline (speedup 1.0000x reference)
#include <cuda_runtime.h>
#include <cuda_bf16.h>
#include <cuda_fp16.h>
#include <math.h>

#define NUM_USERS 100000
#define NUM_ITEMS 50000
#define DIM       64
#define HOP       3
#define NNZ       4000000
#define BATCH     4096
#define NUM_NEG   8
#define NTOT      (NUM_USERS + NUM_ITEMS)          // 150000
#define NELEM     (NTOT * DIM)                     // 9,600,000
#define SLOTS     96                               // max degree (Poisson(26.7), P>=96 ~ 5e-24)
#define MASKW     ((NTOT + 31) / 32)
#define WPB       8                                // warps per block
#define MAXACT    ((2 + NUM_NEG) * BATCH)          // 40960 upper bound on active rows

#define TB        256
#define TOT4      (NELEM / 4)                      // 2,400,000
#define FILL_B    ((NNZ / 2 + TB - 1) / TB)        // 7813
#define INIT_B    ((TOT4 + TB - 1) / TB)           // 9375
#define MASK_B    ((MAXACT + TB - 1) / TB)         // 160

// Scratch state (allocation-free rule: __device__ globals)
__device__ __align__(128) __half g_x0[NELEM];  // fp16 hop buffers (rows 128B)
__device__ __align__(128) __half g_x1[NELEM];
__device__ __align__(128) __half g_x2[NELEM];
__device__ __align__(128) __half g_x3[NELEM];
__device__ int      g_cnt[NTOT];
__device__ unsigned g_mask[MASKW];
__device__ int      g_list[MAXACT];            // compacted active rows for hop 3
__device__ int      g_nactive;
__device__ int2     g_slots[(size_t)NTOT * SLOTS]; // {col*128, half2(val,val)} grouped by row

// ---------------------------------------------------------------------------
// fused preprocessing: blocks [0,FILL_B) build the grouped edge list,
// blocks [FILL_B, FILL_B+INIT_B) build x0, the rest set the hop-3 row mask
// AND append newly-masked rows to the compact list.
// ---------------------------------------------------------------------------
__global__ void __launch_bounds__(TB) fused_pre_kernel(
        const float4* __restrict__ user_emb4,
        const float4* __restrict__ item_emb4,
        const float*  __restrict__ vals,
        const int*    __restrict__ rows,
        const int*    __restrict__ cols,
        const int*    __restrict__ users,
        const int*    __restrict__ items,
        const int*    __restrict__ negs,
        __half* __restrict__ x0) {
    int b = blockIdx.x;
    if (b < FILL_B) {
        // ---- fill: 2 edges per thread (vector loads) ----
        int e = (b * TB + threadIdx.x) * 2;
        if (e >= NNZ) return;
        int2   r2 = *reinterpret_cast<const int2*>(rows + e);
        int2   c2 = *reinterpret_cast<const int2*>(cols + e);
        float2 v2 = *reinterpret_cast<const float2*>(vals + e);

        int pos0 = atomicAdd(&g_cnt[r2.x], 1);
        if (pos0 < SLOTS) {
            __half2 h = __half2half2(__float2half_rn(v2.x));
            g_slots[(size_t)r2.x * SLOTS + pos0] = make_int2(c2.x * 128, *(int*)&h);
        }
        int pos1 = atomicAdd(&g_cnt[r2.y], 1);
        if (pos1 < SLOTS) {
            __half2 h = __half2half2(__float2half_rn(v2.y));
            g_slots[(size_t)r2.y * SLOTS + pos1] = make_int2(c2.y * 128, *(int*)&h);
        }
    } else if (b < FILL_B + INIT_B) {
        // ---- init: x0 = concat(user,item) in fp16 ----
        const int USER4 = NUM_USERS * DIM / 4;
        int i = (b - FILL_B) * TB + threadIdx.x;
        if (i >= TOT4) return;
        float4 v = (i < USER4) ? user_emb4[i] : item_emb4[i - USER4];
        __half2 h0 = __floats2half2_rn(v.x, v.y);
        __half2 h1 = __floats2half2_rn(v.z, v.w);
        uint2 packed = make_uint2(*(unsigned*)&h0, *(unsigned*)&h1);
        *reinterpret_cast<uint2*>(x0 + (size_t)i * 4) = packed;
    } else {
        // ---- mask + compact list of rows needed by the loss ----
        int t = (b - FILL_B - INIT_B) * TB + threadIdx.x;
        int row;
        if (t < BATCH)                       row = __ldg(users + t);
        else if (t < 2 * BATCH)              row = NUM_USERS + __ldg(items + (t - BATCH));
        else if (t < MAXACT)                 row = NUM_USERS + __ldg(negs + (t - 2 * BATCH));
        else return;
        unsigned bit = 1u << (row & 31);
        unsigned old = atomicOr(&g_mask[row >> 5], bit);
        if (!(old & bit)) {
            int p = atomicAdd(&g_nactive, 1);
            g_list[p] = row;
        }
    }
}

// ---------------------------------------------------------------------------
// SpMM, warp per row. 4 lane-groups of 8; group g serves edges e ≡ g (mod 4);
// per 4 edges: 1 LDS.64 broadcast + 1 LDG.128 + 4 HFMA2 per lane.
// Full-row fp16 accumulation (validated in R13); pad to multiple of 8
// (zero-edges -> broadcast loads of row 0, 1 hot line).
// LISTED variant draws its row from the compacted active list (hop 3).
// ---------------------------------------------------------------------------
template <bool LISTED>
__global__ void __launch_bounds__(32 * WPB) spmm_kernel(const __half* __restrict__ x,
                                                        __half* __restrict__ xn) {
    __shared__ int2 sh_edges[WPB][SLOTS + 8];

    int wid  = threadIdx.x >> 5;
    int widx = (blockIdx.x * (32 * WPB) + threadIdx.x) >> 5;
    int lane = threadIdx.x & 31;

    int warp;                                         // destination row
    if (LISTED) {
        if (widx >= g_nactive) return;
        warp = g_list[widx];
    } else {
        if (widx >= NTOT) return;
        warp = widx;
    }

    int deg  = min(g_cnt[warp], SLOTS);
    int dege = (deg + 7) & ~7;                        // pad to multiple of 8
    const int2* row_edges = g_slots + (size_t)warp * SLOTS;
    int2* sh = sh_edges[wid];

    // stage edges (coalesced), zero-pad the tail
    for (int i = lane; i < dege; i += 32)
        sh[i] = (i < deg) ? __ldg(row_edges + i) : make_int2(0, 0);
    __syncwarp();

    const int g  = lane >> 3;                         // edge phase (mod 4)
    const int lo = lane & 7;                          // 16B chunk of the 128B row
    const char* xlane = reinterpret_cast<const char*>(x) + lo * 16;

    __half2 a0 = __float2half2_rn(0.f);
    __half2 a1 = a0, a2 = a0, a3 = a0;

    for (int p = 0; p < dege; p += 8) {               // 8 edges per iter (2 steps)
        int2 ev0 = sh[p + g];                         // LDS.64 broadcast
        int2 ev1 = sh[p + 4 + g];
        uint4 d0 = __ldg(reinterpret_cast<const uint4*>(xlane + ev0.x));
        uint4 d1 = __ldg(reinterpret_cast<const uint4*>(xlane + ev1.x));
        __half2 v0 = *reinterpret_cast<__half2*>(&ev0.y);
        __half2 v1 = *reinterpret_cast<__half2*>(&ev1.y);
        a0 = __hfma2(v0, *reinterpret_cast<__half2*>(&d0.x), a0);
        a1 = __hfma2(v0, *reinterpret_cast<__half2*>(&d0.y), a1);
        a2 = __hfma2(v0, *reinterpret_cast<__half2*>(&d0.z), a2);
        a3 = __hfma2(v0, *reinterpret_cast<__half2*>(&d0.w), a3);
        a0 = __hfma2(v1, *reinterpret_cast<__half2*>(&d1.x), a0);
        a1 = __hfma2(v1, *reinterpret_cast<__half2*>(&d1.y), a1);
        a2 = __hfma2(v1, *reinterpret_cast<__half2*>(&d1.z), a2);
        a3 = __hfma2(v1, *reinterpret_cast<__half2*>(&d1.w), a3);
    }

    // combine the 4 edge-phase groups (lanes lo, lo+8, lo+16, lo+24), fp16
    unsigned u0 = *(unsigned*)&a0, u1 = *(unsigned*)&a1;
    unsigned u2 = *(unsigned*)&a2, u3 = *(unsigned*)&a3;
    #pragma unroll
    for (int o = 16; o >= 8; o >>= 1) {
        unsigned b0 = __shfl_down_sync(0xFFFFFFFFu, u0, o);
        unsigned b1 = __shfl_down_sync(0xFFFFFFFFu, u1, o);
        unsigned b2 = __shfl_down_sync(0xFFFFFFFFu, u2, o);
        unsigned b3 = __shfl_down_sync(0xFFFFFFFFu, u3, o);
        __half2 h;
        h = __hadd2(*(__half2*)&u0, *(__half2*)&b0); u0 = *(unsigned*)&h;
        h = __hadd2(*(__half2*)&u1, *(__half2*)&b1); u1 = *(unsigned*)&h;
        h = __hadd2(*(__half2*)&u2, *(__half2*)&b2); u2 = *(unsigned*)&h;
        h = __hadd2(*(__half2*)&u3, *(__half2*)&b3); u3 = *(unsigned*)&h;
    }

    if (lane < 8) {
        uint4 o = make_uint4(u0, u1, u2, u3);
        reinterpret_cast<uint4*>(xn)[(size_t)warp * 8 + lo] = o;
    }
}

// ---------------------------------------------------------------------------
// InfoNCE loss. One warp per batch element. light_out row assembled on the
// fly: emb(fp32) + x1 + x2 + x3; hop-mean folded in as 1/16 on dot products.
// ---------------------------------------------------------------------------
__device__ __forceinline__ float2 gather_row(const float* __restrict__ emb, int erow,
                                             const __half* __restrict__ x1,
                                             const __half* __restrict__ x2,
                                             const __half* __restrict__ x3,
                                             int grow, int lane) {
    float2 s = *reinterpret_cast<const float2*>(emb + (size_t)erow * DIM + lane * 2);
    size_t o = (size_t)grow * DIM;
    float2 a = __half22float2(__ldg(reinterpret_cast<const __half2*>(x1 + o) + lane));
    float2 b = __half22float2(__ldg(reinterpret_cast<const __half2*>(x2 + o) + lane));
    float2 c = __half22float2(__ldg(reinterpret_cast<const __half2*>(x3 + o) + lane));
    s.x += a.x + b.x + c.x;
    s.y += a.y + b.y + c.y;
    return s;
}

__global__ void loss_kernel(const float* __restrict__ user_emb,
                            const float* __restrict__ item_emb,
                            const __half* __restrict__ x1,
                            const __half* __restrict__ x2,
                            const __half* __restrict__ x3,
                            const int* __restrict__ users,
                            const int* __restrict__ items,
                            const int* __restrict__ negs,
                            float* __restrict__ out) {
    int warp = (blockIdx.x * blockDim.x + threadIdx.x) >> 5;
    int lane = threadIdx.x & 31;
    if (warp >= BATCH) return;

    int u  = __ldg(users + warp);
    int it = __ldg(items + warp);

    float2 uv = gather_row(user_emb, u, x1, x2, x3, u, lane);
    float2 iv = gather_row(item_emb, it, x1, x2, x3, NUM_USERS + it, lane);

    float pos = uv.x * iv.x + uv.y * iv.y;
    #pragma unroll
    for (int o = 16; o; o >>= 1) pos += __shfl_xor_sync(0xFFFFFFFFu, pos, o);
    pos *= 0.0625f;   // (1/4)*(1/4) hop-mean on both operands

    float negsum = 0.f;
    #pragma unroll
    for (int k = 0; k < NUM_NEG; k++) {
        int ni = __ldg(negs + k * BATCH + warp);
        float2 nv = gather_row(item_emb, ni, x1, x2, x3, NUM_USERS + ni, lane);
        float d = uv.x * nv.x + uv.y * nv.y;
        #pragma unroll
        for (int o = 16; o; o >>= 1) d += __shfl_xor_sync(0xFFFFFFFFu, d, o);
        negsum += expf(d * 0.0625f);
    }

    if (lane == 0) {
        float pe = expf(pos);
        float l  = -logf(pe / (pe + negsum));
        atomicAdd(out, l * (1.0f / BATCH));
    }
}

// ---------------------------------------------------------------------------
// launch (single stream; memset nodes + fused preprocessing)
// ---------------------------------------------------------------------------
extern "C" void kernel_launch(void* const* d_in, const int* in_sizes, int n_in,
                              void* d_out, int out_size) {
    const float* user_emb = (const float*)d_in[0];
    const float* item_emb = (const float*)d_in[1];
    const float* A_vals   = (const float*)d_in[2];
    const int*   A_rows   = (const int*)  d_in[3];
    const int*   A_cols   = (const int*)  d_in[4];
    const int*   users    = (const int*)  d_in[5];
    const int*   items    = (const int*)  d_in[6];
    const int*   negs     = (const int*)  d_in[7];
    float* out = (float*)d_out;

    __half *x0, *x1, *x2, *x3;
    int* cntp;
    unsigned* maskp;
    int* nactp;
    cudaGetSymbolAddress((void**)&x0, g_x0);
    cudaGetSymbolAddress((void**)&x1, g_x1);
    cudaGetSymbolAddress((void**)&x2, g_x2);
    cudaGetSymbolAddress((void**)&x3, g_x3);
    cudaGetSymbolAddress((void**)&cntp,  g_cnt);
    cudaGetSymbolAddress((void**)&maskp, g_mask);
    cudaGetSymbolAddress((void**)&nactp, g_nactive);

    // zero counters / mask / list count / output scalar (graph-capturable)
    cudaMemsetAsync(cntp,  0, NTOT  * sizeof(int), 0);
    cudaMemsetAsync(maskp, 0, MASKW * sizeof(unsigned), 0);
    cudaMemsetAsync(nactp, 0, sizeof(int), 0);
    cudaMemsetAsync(out,   0, sizeof(float), 0);

    // fused: fill + init + mask/compact in one launch
    fused_pre_kernel<<<FILL_B + INIT_B + MASK_B, TB>>>(
        (const float4*)user_emb, (const float4*)item_emb,
        A_vals, A_rows, A_cols, users, items, negs, x0);

    // hops 1-2 over all rows; hop 3 over the compacted active list
    const int spmm_blocks = (NTOT + WPB - 1) / WPB;      // warp per row
    const int list_blocks = (MAXACT + WPB - 1) / WPB;    // 5120
    spmm_kernel<false><<<spmm_blocks, 32 * WPB>>>(x0, x1);
    spmm_kernel<false><<<spmm_blocks, 32 * WPB>>>(x1, x2);
    spmm_kernel<true ><<<list_blocks, 32 * WPB>>>(x2, x3);

    loss_kernel<<<(BATCH * 32 + TB - 1) / TB, TB>>>(user_emb, item_emb,
                                                    x1, x2, x3,
                                                    users, items, negs, out);
}

// round 17
// speedup vs baseline: 1.0300x; 1.0300x over previous
#include <cuda_runtime.h>
#include <cuda_bf16.h>
#include <cuda_fp16.h>
#include <math.h>

#define NUM_USERS 100000
#define NUM_ITEMS 50000
#define DIM       64
#define HOP       3
#define NNZ       4000000
#define BATCH     4096
#define NUM_NEG   8
#define NTOT      (NUM_USERS + NUM_ITEMS)          // 150000
#define NELEM     (NTOT * DIM)                     // 9,600,000
#define SLOTS     96                               // max degree (Poisson(26.7), P>=96 ~ 5e-24)
#define MASKW     ((NTOT + 31) / 32)
#define WPB       8                                // warps per block
#define MAXACT    ((2 + NUM_NEG) * BATCH)          // 40960 upper bound on active rows

#define TB        256
#define TOT4      (NELEM / 4)                      // 2,400,000
#define FILL_B    ((NNZ / 4 + TB - 1) / TB)        // 3907  (4 edges per thread)
#define INIT_B    ((TOT4 + TB - 1) / TB)           // 9375
#define MASK_B    ((MAXACT + TB - 1) / TB)         // 160

// Scratch state (allocation-free rule: __device__ globals)
__device__ __align__(128) __half g_x0[NELEM];  // fp16 hop buffers (rows 128B)
__device__ __align__(128) __half g_x1[NELEM];
__device__ __align__(128) __half g_x2[NELEM];
__device__ __align__(128) __half g_x3[NELEM];
__device__ int      g_cnt[NTOT];
__device__ unsigned g_mask[MASKW];
__device__ int      g_list[MAXACT];            // compacted active rows for hop 3
__device__ int      g_nactive;
__device__ int2     g_slots[(size_t)NTOT * SLOTS]; // {col*128, half2(val,val)} grouped by row

// ---------------------------------------------------------------------------
// fused preprocessing: blocks [0,FILL_B) build the grouped edge list
// (4 edges/thread, vector loads, 4 atomics in flight), blocks
// [FILL_B, FILL_B+INIT_B) build x0, the rest set the hop-3 row mask and
// append newly-masked rows to the compact list.
// ---------------------------------------------------------------------------
__global__ void __launch_bounds__(TB) fused_pre_kernel(
        const float4* __restrict__ user_emb4,
        const float4* __restrict__ item_emb4,
        const float*  __restrict__ vals,
        const int*    __restrict__ rows,
        const int*    __restrict__ cols,
        const int*    __restrict__ users,
        const int*    __restrict__ items,
        const int*    __restrict__ negs,
        __half* __restrict__ x0) {
    int b = blockIdx.x;
    if (b < FILL_B) {
        // ---- fill: 4 edges per thread ----
        int e = (b * TB + threadIdx.x) * 4;
        if (e >= NNZ) return;
        int4   r4 = *reinterpret_cast<const int4*>(rows + e);
        int4   c4 = *reinterpret_cast<const int4*>(cols + e);
        float4 v4 = *reinterpret_cast<const float4*>(vals + e);

        // issue all 4 atomics first (MLP 4 on the return latency)
        int p0 = atomicAdd(&g_cnt[r4.x], 1);
        int p1 = atomicAdd(&g_cnt[r4.y], 1);
        int p2 = atomicAdd(&g_cnt[r4.z], 1);
        int p3 = atomicAdd(&g_cnt[r4.w], 1);

        if (p0 < SLOTS) {
            __half2 h = __half2half2(__float2half_rn(v4.x));
            g_slots[(size_t)r4.x * SLOTS + p0] = make_int2(c4.x * 128, *(int*)&h);
        }
        if (p1 < SLOTS) {
            __half2 h = __half2half2(__float2half_rn(v4.y));
            g_slots[(size_t)r4.y * SLOTS + p1] = make_int2(c4.y * 128, *(int*)&h);
        }
        if (p2 < SLOTS) {
            __half2 h = __half2half2(__float2half_rn(v4.z));
            g_slots[(size_t)r4.z * SLOTS + p2] = make_int2(c4.z * 128, *(int*)&h);
        }
        if (p3 < SLOTS) {
            __half2 h = __half2half2(__float2half_rn(v4.w));
            g_slots[(size_t)r4.w * SLOTS + p3] = make_int2(c4.w * 128, *(int*)&h);
        }
    } else if (b < FILL_B + INIT_B) {
        // ---- init: x0 = concat(user,item) in fp16 ----
        const int USER4 = NUM_USERS * DIM / 4;
        int i = (b - FILL_B) * TB + threadIdx.x;
        if (i >= TOT4) return;
        float4 v = (i < USER4) ? user_emb4[i] : item_emb4[i - USER4];
        __half2 h0 = __floats2half2_rn(v.x, v.y);
        __half2 h1 = __floats2half2_rn(v.z, v.w);
        uint2 packed = make_uint2(*(unsigned*)&h0, *(unsigned*)&h1);
        *reinterpret_cast<uint2*>(x0 + (size_t)i * 4) = packed;
    } else {
        // ---- mask + compact list of rows needed by the loss ----
        int t = (b - FILL_B - INIT_B) * TB + threadIdx.x;
        int row;
        if (t < BATCH)                       row = __ldg(users + t);
        else if (t < 2 * BATCH)              row = NUM_USERS + __ldg(items + (t - BATCH));
        else if (t < MAXACT)                 row = NUM_USERS + __ldg(negs + (t - 2 * BATCH));
        else return;
        unsigned bit = 1u << (row & 31);
        unsigned old = atomicOr(&g_mask[row >> 5], bit);
        if (!(old & bit)) {
            int p = atomicAdd(&g_nactive, 1);
            g_list[p] = row;
        }
    }
}

// ---------------------------------------------------------------------------
// SpMM, warp per row (R15 inner loop, verbatim — frozen). LISTED variant
// draws its row from the compacted active list (hop 3). Edge list staged in
// smem (padded to multiple of 8 with zero-edges); one LDS.64 broadcast per
// edge-pair; fp16 HFMA2 chain of 8 drained to fp32 per 8 edges.
// ---------------------------------------------------------------------------
template <bool LISTED>
__global__ void __launch_bounds__(32 * WPB) spmm_kernel(const __half* __restrict__ x,
                                                        __half* __restrict__ xn) {
    __shared__ int2 sh_edges[WPB][SLOTS + 8];

    int wid  = threadIdx.x >> 5;
    int widx = (blockIdx.x * (32 * WPB) + threadIdx.x) >> 5;
    int lane = threadIdx.x & 31;

    int warp;                                         // destination row
    if (LISTED) {
        if (widx >= g_nactive) return;
        warp = g_list[widx];
    } else {
        if (widx >= NTOT) return;
        warp = widx;
    }

    int deg  = min(g_cnt[warp], SLOTS);
    int dege = (deg + 7) & ~7;                        // pad to multiple of 8
    const int2* row_edges = g_slots + (size_t)warp * SLOTS;
    int2* sh = sh_edges[wid];

    // stage edges (coalesced), zero-pad the tail
    for (int i = lane; i < dege; i += 32)
        sh[i] = (i < deg) ? __ldg(row_edges + i) : make_int2(0, 0);
    __syncwarp();

    const int hi = lane >> 4;                         // edge parity served
    const int lo = lane & 15;                         // 8B chunk of the 128B row
    const char* xlane = reinterpret_cast<const char*>(x) + lo * 8;

    float f0 = 0.f, f1 = 0.f, f2 = 0.f, f3 = 0.f;

    for (int p = 0; p < dege; p += 8) {               // 8 edges per drain
        __half2 a0 = __float2half2_rn(0.f);
        __half2 a1 = a0;
        #pragma unroll
        for (int u = 0; u < 4; u++) {
            int2 ev = sh[p + 2 * u + hi];             // LDS.64 broadcast
            uint2 d = __ldg(reinterpret_cast<const uint2*>(xlane + ev.x));
            __half2 vv = *reinterpret_cast<__half2*>(&ev.y);
            a0 = __hfma2(vv, *reinterpret_cast<__half2*>(&d.x), a0);
            a1 = __hfma2(vv, *reinterpret_cast<__half2*>(&d.y), a1);
        }
        float2 t0 = __half22float2(a0);
        float2 t1 = __half22float2(a1);
        f0 += t0.x; f1 += t0.y;
        f2 += t1.x; f3 += t1.y;
    }

    // combine even-edge (lanes 0-15) and odd-edge (lanes 16-31) partials
    f0 += __shfl_down_sync(0xFFFFFFFFu, f0, 16);
    f1 += __shfl_down_sync(0xFFFFFFFFu, f1, 16);
    f2 += __shfl_down_sync(0xFFFFFFFFu, f2, 16);
    f3 += __shfl_down_sync(0xFFFFFFFFu, f3, 16);

    if (lane < 16) {
        __half2 h0 = __floats2half2_rn(f0, f1);
        __half2 h1 = __floats2half2_rn(f2, f3);
        uint2 o = make_uint2(*(unsigned*)&h0, *(unsigned*)&h1);
        reinterpret_cast<uint2*>(xn)[(size_t)warp * 16 + lo] = o;
    }
}

// ---------------------------------------------------------------------------
// InfoNCE loss. One warp per batch element. light_out row assembled on the
// fly: emb(fp32) + x1 + x2 + x3; hop-mean folded in as 1/16 on dot products.
// ---------------------------------------------------------------------------
__device__ __forceinline__ float2 gather_row(const float* __restrict__ emb, int erow,
                                             const __half* __restrict__ x1,
                                             const __half* __restrict__ x2,
                                             const __half* __restrict__ x3,
                                             int grow, int lane) {
    float2 s = *reinterpret_cast<const float2*>(emb + (size_t)erow * DIM + lane * 2);
    size_t o = (size_t)grow * DIM;
    float2 a = __half22float2(__ldg(reinterpret_cast<const __half2*>(x1 + o) + lane));
    float2 b = __half22float2(__ldg(reinterpret_cast<const __half2*>(x2 + o) + lane));
    float2 c = __half22float2(__ldg(reinterpret_cast<const __half2*>(x3 + o) + lane));
    s.x += a.x + b.x + c.x;
    s.y += a.y + b.y + c.y;
    return s;
}

__global__ void loss_kernel(const float* __restrict__ user_emb,
                            const float* __restrict__ item_emb,
                            const __half* __restrict__ x1,
                            const __half* __restrict__ x2,
                            const __half* __restrict__ x3,
                            const int* __restrict__ users,
                            const int* __restrict__ items,
                            const int* __restrict__ negs,
                            float* __restrict__ out) {
    int warp = (blockIdx.x * blockDim.x + threadIdx.x) >> 5;
    int lane = threadIdx.x & 31;
    if (warp >= BATCH) return;

    int u  = __ldg(users + warp);
    int it = __ldg(items + warp);

    float2 uv = gather_row(user_emb, u, x1, x2, x3, u, lane);
    float2 iv = gather_row(item_emb, it, x1, x2, x3, NUM_USERS + it, lane);

    float pos = uv.x * iv.x + uv.y * iv.y;
    #pragma unroll
    for (int o = 16; o; o >>= 1) pos += __shfl_xor_sync(0xFFFFFFFFu, pos, o);
    pos *= 0.0625f;   // (1/4)*(1/4) hop-mean on both operands

    float negsum = 0.f;
    #pragma unroll
    for (int k = 0; k < NUM_NEG; k++) {
        int ni = __ldg(negs + k * BATCH + warp);
        float2 nv = gather_row(item_emb, ni, x1, x2, x3, NUM_USERS + ni, lane);
        float d = uv.x * nv.x + uv.y * nv.y;
        #pragma unroll
        for (int o = 16; o; o >>= 1) d += __shfl_xor_sync(0xFFFFFFFFu, d, o);
        negsum += expf(d * 0.0625f);
    }

    if (lane == 0) {
        float pe = expf(pos);
        float l  = -logf(pe / (pe + negsum));
        atomicAdd(out, l * (1.0f / BATCH));
    }
}

// ---------------------------------------------------------------------------
// launch (single stream; memset nodes + fused preprocessing)
// ---------------------------------------------------------------------------
extern "C" void kernel_launch(void* const* d_in, const int* in_sizes, int n_in,
                              void* d_out, int out_size) {
    const float* user_emb = (const float*)d_in[0];
    const float* item_emb = (const float*)d_in[1];
    const float* A_vals   = (const float*)d_in[2];
    const int*   A_rows   = (const int*)  d_in[3];
    const int*   A_cols   = (const int*)  d_in[4];
    const int*   users    = (const int*)  d_in[5];
    const int*   items    = (const int*)  d_in[6];
    const int*   negs     = (const int*)  d_in[7];
    float* out = (float*)d_out;

    __half *x0, *x1, *x2, *x3;
    int* cntp;
    unsigned* maskp;
    int* nactp;
    cudaGetSymbolAddress((void**)&x0, g_x0);
    cudaGetSymbolAddress((void**)&x1, g_x1);
    cudaGetSymbolAddress((void**)&x2, g_x2);
    cudaGetSymbolAddress((void**)&x3, g_x3);
    cudaGetSymbolAddress((void**)&cntp,  g_cnt);
    cudaGetSymbolAddress((void**)&maskp, g_mask);
    cudaGetSymbolAddress((void**)&nactp, g_nactive);

    // zero counters / mask / list count / output scalar (graph-capturable)
    cudaMemsetAsync(cntp,  0, NTOT  * sizeof(int), 0);
    cudaMemsetAsync(maskp, 0, MASKW * sizeof(unsigned), 0);
    cudaMemsetAsync(nactp, 0, sizeof(int), 0);
    cudaMemsetAsync(out,   0, sizeof(float), 0);

    // fused: fill + init + mask/compact in one launch
    fused_pre_kernel<<<FILL_B + INIT_B + MASK_B, TB>>>(
        (const float4*)user_emb, (const float4*)item_emb,
        A_vals, A_rows, A_cols, users, items, negs, x0);

    // hops 1-2 over all rows; hop 3 over the compacted active list
    const int spmm_blocks = (NTOT + WPB - 1) / WPB;      // warp per row
    const int list_blocks = (MAXACT + WPB - 1) / WPB;    // 5120
    spmm_kernel<false><<<spmm_blocks, 32 * WPB>>>(x0, x1);
    spmm_kernel<false><<<spmm_blocks, 32 * WPB>>>(x1, x2);
    spmm_kernel<true ><<<list_blocks, 32 * WPB>>>(x2, x3);

    loss_kernel<<<(BATCH * 32 + TB - 1) / TB, TB>>>(user_emb, item_emb,
                                                    x1, x2, x3,
                                                    users, items, negs, out);
}